// round 2
// baseline (speedup 1.0000x reference)
#include <cuda_runtime.h>
#include <cuda_bf16.h>

#define BINS 30
#define TPB  128
#define GRID 888   // 148 SMs * 6 blocks; 6*30KB = 184KB smem/SM

__device__ float2 g_part[GRID * BINS];
__device__ unsigned int g_ctr = 0;

__device__ __forceinline__ float rcp_approx(float x) {
    float r;
    asm("rcp.approx.f32 %0, %1;" : "=f"(r) : "f"(x));
    return r;
}

// u = x_other - x_true.  g = sigmoid(u) = 1 - 1/(1+e^u),  ce = log(1+e^u).
__device__ __forceinline__ void ghm_elem(float x0, float x1, int t, float2* hrow) {
    float diff = x1 - x0;                                        // FADD
    float u = __int_as_float(__float_as_int(diff) ^ (t << 31));  // SHF + LOP3
    float e = __expf(u);                                         // FMUL + MUFU.EX2
    float s = 1.0f + e;                                          // FADD
    float r = rcp_approx(s);                                     // MUFU.RCP
    float bin_f = fmaf(r, -30.0f, 30.0f);                        // FFMA  (= 30*g)
    bin_f = fminf(bin_f, 29.0f);                                 // FMNMX
    int bin = (int)bin_f;                                        // F2I (trunc; bin_f >= -eps -> 0)
    float lg = __log2f(s);                                       // MUFU.LG2

    float2 h = hrow[bin * TPB];                                  // IMAD + LDS.64
    h.x += 1.0f;                                                 // FADD
    h.y = fmaf(lg, 0.69314718056f, h.y);                         // FFMA (ce = lg*ln2)
    hrow[bin * TPB] = h;                                         // STS.64
}

__global__ void __launch_bounds__(TPB) ghm_fused(const float4* __restrict__ x4,
                                                 const int4* __restrict__ t4,
                                                 const float2* __restrict__ x2,
                                                 const int* __restrict__ tgt,
                                                 int B,
                                                 float* __restrict__ out,
                                                 int out_size) {
    __shared__ float2 hist[BINS * TPB];   // hist[bin*TPB + tid]: conflict-free
    int tid = threadIdx.x;

    #pragma unroll
    for (int b = 0; b < BINS; b++) hist[b * TPB + tid] = make_float2(0.0f, 0.0f);
    __syncthreads();

    float2* hrow = &hist[tid];

    int gt = blockIdx.x * TPB + tid;
    int nthreads = GRID * TPB;
    int ngroups = B >> 3;                 // groups of 8 elements

    for (int grp = gt; grp < ngroups; grp += nthreads) {
        float4 a = x4[grp * 4 + 0];
        float4 b = x4[grp * 4 + 1];
        float4 c = x4[grp * 4 + 2];
        float4 d = x4[grp * 4 + 3];
        int4 ta = t4[grp * 2 + 0];
        int4 tb = t4[grp * 2 + 1];
        ghm_elem(a.x, a.y, ta.x, hrow);
        ghm_elem(a.z, a.w, ta.y, hrow);
        ghm_elem(b.x, b.y, ta.z, hrow);
        ghm_elem(b.z, b.w, ta.w, hrow);
        ghm_elem(c.x, c.y, tb.x, hrow);
        ghm_elem(c.z, c.w, tb.y, hrow);
        ghm_elem(d.x, d.y, tb.z, hrow);
        ghm_elem(d.z, d.w, tb.w, hrow);
    }
    // scalar tail
    for (int j = (ngroups << 3) + gt; j < B; j += nthreads) {
        float2 xv = x2[j];
        ghm_elem(xv.x, xv.y, tgt[j], hrow);
    }

    __syncthreads();

    // tree-reduce columns per bin
    for (int s = TPB / 2; s > 0; s >>= 1) {
        if (tid < s) {
            #pragma unroll
            for (int b = 0; b < BINS; b++) {
                float2 p = hist[b * TPB + tid];
                float2 q = hist[b * TPB + tid + s];
                p.x += q.x; p.y += q.y;
                hist[b * TPB + tid] = p;
            }
        }
        __syncthreads();
    }

    // write per-block partials (no atomics, no pre-zero needed)
    if (tid < BINS) g_part[blockIdx.x * BINS + tid] = hist[tid * TPB];
    __threadfence();
    __syncthreads();

    __shared__ bool is_last;
    if (tid == 0) {
        unsigned prev = atomicAdd(&g_ctr, 1u);
        is_last = (prev == GRID - 1);
    }
    __syncthreads();
    if (!is_last) return;

    __threadfence();  // acquire partials written by other blocks

    // re-zero hist, accumulate all partials into private columns, tree-reduce
    #pragma unroll
    for (int b = 0; b < BINS; b++) hist[b * TPB + tid] = make_float2(0.0f, 0.0f);
    __syncthreads();

    for (int i = tid; i < GRID * BINS; i += TPB) {
        float2 v = g_part[i];
        int b = i % BINS;
        float2 h = hrow[b * TPB];
        h.x += v.x; h.y += v.y;
        hrow[b * TPB] = h;
    }
    __syncthreads();

    for (int s = TPB / 2; s > 0; s >>= 1) {
        if (tid < s) {
            #pragma unroll
            for (int b = 0; b < BINS; b++) {
                float2 p = hist[b * TPB + tid];
                float2 q = hist[b * TPB + tid + s];
                p.x += q.x; p.y += q.y;
                hist[b * TPB + tid] = p;
            }
        }
        __syncthreads();
    }

    if (tid < 32) {
        float cnt = (tid < BINS) ? hist[tid * TPB].x : 0.0f;
        float ces = (tid < BINS) ? hist[tid * TPB].y : 0.0f;
        float nz   = (cnt > 0.0f) ? 1.0f : 0.0f;
        float term = (cnt > 0.0f) ? ces / (0.25f * cnt) : 0.0f;
        #pragma unroll
        for (int o = 16; o > 0; o >>= 1) {
            nz   += __shfl_xor_sync(0xFFFFFFFFu, nz,   o);
            term += __shfl_xor_sync(0xFFFFFFFFu, term, o);
        }
        if (tid == 0) {
            float loss = term / fmaxf(nz, 1.0f);
            for (int i = 0; i < out_size; i++) out[i] = loss;
            g_ctr = 0;  // reset for next graph replay
        }
    }
}

extern "C" void kernel_launch(void* const* d_in, const int* in_sizes, int n_in,
                              void* d_out, int out_size) {
    const float* x   = (const float*)d_in[0];
    const int*   tgt = (const int*)d_in[1];
    int B = in_sizes[1];   // target element count == batch size

    ghm_fused<<<GRID, TPB>>>((const float4*)x, (const int4*)tgt,
                             (const float2*)x, tgt, B,
                             (float*)d_out, out_size);
}

// round 4
// speedup vs baseline: 1.0961x; 1.0961x over previous
#include <cuda_runtime.h>
#include <cuda_bf16.h>

#define BINS 30
#define TPB  128
#define GRID 592   // 148 SMs * 4 blocks; 4 * 30.7KB smem/SM

__device__ float2 g_part[GRID * BINS];
__device__ unsigned int g_ctr = 0;

__device__ __forceinline__ float rcp_approx(float x) {
    float r;
    asm("rcp.approx.f32 %0, %1;" : "=f"(r) : "f"(x));
    return r;
}

// u = x_other - x_true.  g = sigmoid(u) = 1 - 1/(1+e^u),  ce = log(1+e^u).
__device__ __forceinline__ void ghm_elem(float x0, float x1, int t, float2* hrow) {
    float diff = x1 - x0;                                        // FADD
    float u = __int_as_float(__float_as_int(diff) ^ (t << 31));  // SHF + LOP3
    float e = __expf(u);                                         // FMUL + MUFU.EX2
    float s = 1.0f + e;                                          // FADD
    float r = rcp_approx(s);                                     // MUFU.RCP
    float bin_f = fmaf(r, -30.0f, 30.0f);                        // FFMA  (= 30*g)
    bin_f = fminf(bin_f, 29.0f);                                 // FMNMX
    int bin = (int)bin_f;                                        // F2I
    float lg = __log2f(s);                                       // MUFU.LG2

    float2 h = hrow[bin * TPB];                                  // LDS.64
    h.x += 1.0f;                                                 // FADD
    h.y = fmaf(lg, 0.69314718056f, h.y);                         // FFMA (ce = lg*ln2)
    hrow[bin * TPB] = h;                                         // STS.64
}

__global__ void __launch_bounds__(TPB) ghm_fused(const float4* __restrict__ x4,
                                                 const int4* __restrict__ t4,
                                                 const float2* __restrict__ x2,
                                                 const int* __restrict__ tgt,
                                                 int B,
                                                 float* __restrict__ out,
                                                 int out_size) {
    __shared__ float2 hist[BINS * TPB];   // hist[bin*TPB + tid]: conflict-free
    int tid = threadIdx.x;

    #pragma unroll
    for (int b = 0; b < BINS; b++) hist[b * TPB + tid] = make_float2(0.0f, 0.0f);
    __syncthreads();

    float2* hrow = &hist[tid];

    int gt = blockIdx.x * TPB + tid;
    const int nthreads = GRID * TPB;
    int ngroups = B >> 2;                 // groups of 4 elements

    // software-pipelined grid-stride loop: prefetch next group's 48B while
    // processing the current group, so DRAM latency overlaps compute.
    int grp = gt;
    if (grp < ngroups) {
        float4 ca = x4[grp * 2 + 0];
        float4 cb = x4[grp * 2 + 1];
        int4   ct = t4[grp];
        int nxt = grp + nthreads;
        while (nxt < ngroups) {
            float4 na = x4[nxt * 2 + 0];
            float4 nb = x4[nxt * 2 + 1];
            int4   nt = t4[nxt];
            ghm_elem(ca.x, ca.y, ct.x, hrow);
            ghm_elem(ca.z, ca.w, ct.y, hrow);
            ghm_elem(cb.x, cb.y, ct.z, hrow);
            ghm_elem(cb.z, cb.w, ct.w, hrow);
            ca = na; cb = nb; ct = nt;
            nxt += nthreads;
        }
        ghm_elem(ca.x, ca.y, ct.x, hrow);
        ghm_elem(ca.z, ca.w, ct.y, hrow);
        ghm_elem(cb.x, cb.y, ct.z, hrow);
        ghm_elem(cb.z, cb.w, ct.w, hrow);
    }
    // scalar tail (B % 4 != 0)
    for (int j = (ngroups << 2) + gt; j < B; j += nthreads) {
        float2 xv = x2[j];
        ghm_elem(xv.x, xv.y, tgt[j], hrow);
    }

    __syncthreads();

    // tree-reduce columns per bin
    for (int s = TPB / 2; s > 0; s >>= 1) {
        if (tid < s) {
            #pragma unroll
            for (int b = 0; b < BINS; b++) {
                float2 p = hist[b * TPB + tid];
                float2 q = hist[b * TPB + tid + s];
                p.x += q.x; p.y += q.y;
                hist[b * TPB + tid] = p;
            }
        }
        __syncthreads();
    }

    // write per-block partials (no atomics, no pre-zero needed)
    if (tid < BINS) g_part[blockIdx.x * BINS + tid] = hist[tid * TPB];
    __threadfence();
    __syncthreads();

    __shared__ bool is_last;
    if (tid == 0) {
        unsigned prev = atomicAdd(&g_ctr, 1u);
        is_last = (prev == GRID - 1);
    }
    __syncthreads();
    if (!is_last) return;

    __threadfence();  // acquire partials written by other blocks

    // re-zero hist, accumulate all partials, tree-reduce
    #pragma unroll
    for (int b = 0; b < BINS; b++) hist[b * TPB + tid] = make_float2(0.0f, 0.0f);
    __syncthreads();

    for (int i = tid; i < GRID * BINS; i += TPB) {
        float2 v = g_part[i];
        int b = i % BINS;
        float2 h = hrow[b * TPB];
        h.x += v.x; h.y += v.y;
        hrow[b * TPB] = h;
    }
    __syncthreads();

    for (int s = TPB / 2; s > 0; s >>= 1) {
        if (tid < s) {
            #pragma unroll
            for (int b = 0; b < BINS; b++) {
                float2 p = hist[b * TPB + tid];
                float2 q = hist[b * TPB + tid + s];
                p.x += q.x; p.y += q.y;
                hist[b * TPB + tid] = p;
            }
        }
        __syncthreads();
    }

    if (tid < 32) {
        float cnt = (tid < BINS) ? hist[tid * TPB].x : 0.0f;
        float ces = (tid < BINS) ? hist[tid * TPB].y : 0.0f;
        float nz   = (cnt > 0.0f) ? 1.0f : 0.0f;
        float term = (cnt > 0.0f) ? ces / (0.25f * cnt) : 0.0f;
        #pragma unroll
        for (int o = 16; o > 0; o >>= 1) {
            nz   += __shfl_xor_sync(0xFFFFFFFFu, nz,   o);
            term += __shfl_xor_sync(0xFFFFFFFFu, term, o);
        }
        if (tid == 0) {
            float loss = term / fmaxf(nz, 1.0f);
            for (int i = 0; i < out_size; i++) out[i] = loss;
            g_ctr = 0;  // reset for next graph replay
        }
    }
}

extern "C" void kernel_launch(void* const* d_in, const int* in_sizes, int n_in,
                              void* d_out, int out_size) {
    const float* x   = (const float*)d_in[0];
    const int*   tgt = (const int*)d_in[1];
    int B = in_sizes[1];   // target element count == batch size

    ghm_fused<<<GRID, TPB>>>((const float4*)x, (const int4*)tgt,
                             (const float2*)x, tgt, B,
                             (float*)d_out, out_size);
}